// round 4
// baseline (speedup 1.0000x reference)
#include <cuda_runtime.h>
#include <math.h>

#define NATOMS 120000
#define MM 12
#define AFL 64
#define EFL 41
#define C2 128            // 2*AFL
#define NCONV 3
#define NCRYS 2400
#define ORIG 92
#define NTYPES 100
#define HFL 128
#define GRID_S 592
#define GRID_A 592
#define GRID_P 592
#define STEPF 0.2f
#define EPSF 1e-5f
#define NEDGE (NATOMS*MM)
#define FULLM 0xffffffffu

// ---------------- device scratch ----------------
__device__ float g_embed[NTYPES*AFL];
__device__ float g_x[NATOMS*AFL];
__device__ float g_xW[NATOMS*2*C2];          // [N,256]: 0..127 self, 128..255 nbr
__device__ float g_summed[NATOMS*AFL];
__device__ float g_partS[GRID_S*768];
__device__ float g_part2[GRID_A*128];
__device__ float g_scale1[C2], g_shift1[C2], g_scale2[AFL], g_shift2[AFL];
// distance-only precompute (fixed-point, deterministic)
__device__ unsigned int       g_deg[NATOMS];
__device__ unsigned int       g_RU[NATOMS*48];     // R_j[41] scaled 2^24
__device__ unsigned int       g_GnU[NATOMS*48];    // Gn[41]  scaled 2^24
__device__ unsigned long long g_HU[EFL*EFL];       // H scaled 2^30

__device__ __forceinline__ float spf(float x){ return fmaxf(x,0.f) + __logf(1.f + __expf(-fabsf(x))); }
__device__ __forceinline__ float sigf(float x){ return __fdividef(1.f, 1.f + __expf(-x)); }

#define FMA4(Zv,Gv,Wv) { (Zv).x=fmaf((Gv),(Wv).x,(Zv).x); (Zv).y=fmaf((Gv),(Wv).y,(Zv).y); (Zv).z=fmaf((Gv),(Wv).z,(Zv).z); (Zv).w=fmaf((Gv),(Wv).w,(Zv).w); }
#define ADD4(Zv,Wv)    { (Zv).x+=(Wv).x; (Zv).y+=(Wv).y; (Zv).z+=(Wv).z; (Zv).w+=(Wv).w; }

// ---------------- zero fixed-point accumulators ----------------
__global__ void k_zero(){
    int i = blockIdx.x*blockDim.x + threadIdx.x;
    int stride = gridDim.x*blockDim.x;
    for(int t=i; t<NATOMS*48; t+=stride){ g_RU[t]=0u; g_GnU[t]=0u; }
    for(int t=i; t<NATOMS; t+=stride) g_deg[t]=0u;
    for(int t=i; t<EFL*EFL; t+=stride) g_HU[t]=0ull;
}

// ---------------- per-edge distance precompute (once) ----------------
__global__ void k_prep(const int* __restrict__ nidx, const float* __restrict__ nd){
    __shared__ unsigned long long Hs[EFL*EFL];
    for(int i=threadIdx.x;i<EFL*EFL;i+=blockDim.x) Hs[i]=0ull;
    __syncthreads();
    const int warp = threadIdx.x>>5, lane = threadIdx.x&31;
    for(int e = blockIdx.x*8 + warp; e < NEDGE; e += GRID_P*8){
        int n = e/MM;
        int j = nidx[e];
        float d = nd[e];
        int kc = __float2int_rn(d*5.0f);
        int ks = min(max(kc-3,0), EFL-8);
        float g = 0.f;
        if(lane < 8){
            float u = d - STEPF*(float)(ks+lane);
            g = expf(-u*u*25.0f);
            unsigned fx = (unsigned)(g*16777216.f);
            if(fx){
                atomicAdd(&g_RU[j*48+ks+lane], fx);
                atomicAdd(&g_GnU[n*48+ks+lane], fx);
            }
        }
        if(lane==0) atomicAdd(&g_deg[j], 1u);
        int t2 = lane&7, t1 = lane>>3;
        float gg2 = __shfl_sync(FULLM, g, t2);
        float gg1 = __shfl_sync(FULLM, g, t1);
        float gg1b= __shfl_sync(FULLM, g, t1+4);
        unsigned long long p1 = (unsigned long long)(gg1 *gg2*1073741824.f);
        unsigned long long p2 = (unsigned long long)(gg1b*gg2*1073741824.f);
        if(p1) atomicAdd(&Hs[(ks+t1  )*EFL + ks+t2], p1);
        if(p2) atomicAdd(&Hs[(ks+t1+4)*EFL + ks+t2], p2);
    }
    __syncthreads();
    for(int i=threadIdx.x;i<EFL*EFL;i+=blockDim.x) if(Hs[i]) atomicAdd(&g_HU[i], Hs[i]);
}

// ---------------- embed table: atom_table @ W_embed ----------------
__global__ void k_embed(const float* __restrict__ at, const float* __restrict__ we){
    int t = blockIdx.x, c = threadIdx.x;
    float s = 0.f;
    for(int o=0;o<ORIG;o++) s = fmaf(at[t*ORIG+o], we[o*AFL+c], s);
    g_embed[t*AFL+c] = s;
}

__global__ void k_gatherx(const int* __restrict__ af){
    int i = blockIdx.x*blockDim.x + threadIdx.x;
    if(i < NATOMS*AFL){
        int n = i >> 6, c = i & 63;
        g_x[i] = g_embed[af[n]*AFL + c];
    }
}

// ---------------- xW gemm: [N,64] @ [64,256] ----------------
__global__ void k_gemm(const float* __restrict__ W){
    __shared__ __align__(16) float sW[64][132];
    __shared__ float sX[32][65];
    const int half = blockIdx.y;
    for(int i=threadIdx.x;i<64*C2;i+=256){
        int k = i >> 7, c = i & 127;
        sW[k][c] = W[(half*AFL + k)*C2 + c];
    }
    const int tx = threadIdx.x & 31;
    const int ty = threadIdx.x >> 5;
    for(int tile=blockIdx.x; tile < NATOMS/32; tile += gridDim.x){
        const int row0 = tile*32;
        __syncthreads();
        for(int i=threadIdx.x;i<32*AFL;i+=256){
            int r = i >> 6, k = i & 63;
            sX[r][k] = g_x[(row0+r)*AFL + k];
        }
        __syncthreads();
        float acc[4][4];
        #pragma unroll
        for(int r=0;r<4;r++){
            #pragma unroll
            for(int c=0;c<4;c++) acc[r][c]=0.f;
        }
        #pragma unroll
        for(int k=0;k<AFL;k++){
            float4 wv = *(const float4*)&sW[k][tx*4];
            #pragma unroll
            for(int r=0;r<4;r++){
                float xv = sX[ty*4+r][k];
                acc[r][0] = fmaf(xv, wv.x, acc[r][0]);
                acc[r][1] = fmaf(xv, wv.y, acc[r][1]);
                acc[r][2] = fmaf(xv, wv.z, acc[r][2]);
                acc[r][3] = fmaf(xv, wv.w, acc[r][3]);
            }
        }
        #pragma unroll
        for(int r=0;r<4;r++){
            float4 o = make_float4(acc[r][0],acc[r][1],acc[r][2],acc[r][3]);
            *(float4*)&g_xW[(row0+ty*4+r)*(2*C2) + half*C2 + tx*4] = o;
        }
    }
}

// ---------------- per-atom analytic BN1 stats ----------------
__global__ __launch_bounds__(256) void k_stats(const float* __restrict__ Wc,
                                               const float* __restrict__ bias,
                                               const int* __restrict__ nidx){
    __shared__ __align__(16) float sWe[EFL][132];
    __shared__ float sP[8][384];
    for(int i=threadIdx.x;i<EFL*C2;i+=256){
        int k = i>>7, c = i&127;
        sWe[k][c] = Wc[(C2+k)*C2 + c];
    }
    __syncthreads();
    const int warp = threadIdx.x>>5, lane = threadIdx.x&31;
    float4 bb = *(const float4*)&bias[lane*4];
    float4 sa = make_float4(0,0,0,0), sa2 = sa, sb = sa, sb2 = sa, su = sa, sx = sa;
    for(int n = blockIdx.x*8 + warp; n < NATOMS; n += GRID_S*8){
        float4 a = *(const float4*)&g_xW[n*(2*C2) + lane*4];
        a.x += bb.x; a.y += bb.y; a.z += bb.z; a.w += bb.w;
        float4 b = *(const float4*)&g_xW[n*(2*C2) + C2 + lane*4];
        int myi = (lane < MM) ? nidx[n*MM + lane] : 0;
        float4 SB = make_float4(0,0,0,0);
        #pragma unroll 1
        for(int m=0;m<MM;m++){
            int j = __shfl_sync(FULLM, myi, m);
            float4 bj = *(const float4*)&g_xW[j*(2*C2) + C2 + lane*4];
            ADD4(SB, bj);
        }
        const float inv24 = 1.f/16777216.f;
        float ga = (float)g_GnU[n*48+lane] * inv24;
        float gb = (lane<9) ? (float)g_GnU[n*48+32+lane] * inv24 : 0.f;
        float ra = (float)g_RU[n*48+lane] * inv24;
        float rb = (lane<9) ? (float)g_RU[n*48+32+lane] * inv24 : 0.f;
        float degf = (float)g_deg[n];
        float4 u = make_float4(0,0,0,0), v = u;
        #pragma unroll
        for(int k=0;k<EFL;k++){
            float g = __shfl_sync(FULLM, (k<32)?ga:gb, k&31);
            float r = __shfl_sync(FULLM, (k<32)?ra:rb, k&31);
            float4 w4 = *(const float4*)&sWe[k][lane*4];
            FMA4(u, g, w4);
            FMA4(v, r, w4);
        }
        ADD4(sa, a);
        sa2.x = fmaf(a.x,a.x,sa2.x); sa2.y = fmaf(a.y,a.y,sa2.y);
        sa2.z = fmaf(a.z,a.z,sa2.z); sa2.w = fmaf(a.w,a.w,sa2.w);
        sb.x  = fmaf(degf,b.x,sb.x);  sb.y  = fmaf(degf,b.y,sb.y);
        sb.z  = fmaf(degf,b.z,sb.z);  sb.w  = fmaf(degf,b.w,sb.w);
        sb2.x = fmaf(degf*b.x,b.x,sb2.x); sb2.y = fmaf(degf*b.y,b.y,sb2.y);
        sb2.z = fmaf(degf*b.z,b.z,sb2.z); sb2.w = fmaf(degf*b.w,b.w,sb2.w);
        ADD4(su, u);
        sx.x += a.x*SB.x + a.x*u.x + b.x*v.x;
        sx.y += a.y*SB.y + a.y*u.y + b.y*v.y;
        sx.z += a.z*SB.z + a.z*u.z + b.z*v.z;
        sx.w += a.w*SB.w + a.w*u.w + b.w*v.w;
    }
    // round 1: sa, sa2, sb
    sP[warp][lane*4+0]=sa.x;  sP[warp][lane*4+1]=sa.y;  sP[warp][lane*4+2]=sa.z;  sP[warp][lane*4+3]=sa.w;
    sP[warp][128+lane*4+0]=sa2.x; sP[warp][128+lane*4+1]=sa2.y; sP[warp][128+lane*4+2]=sa2.z; sP[warp][128+lane*4+3]=sa2.w;
    sP[warp][256+lane*4+0]=sb.x;  sP[warp][256+lane*4+1]=sb.y;  sP[warp][256+lane*4+2]=sb.z;  sP[warp][256+lane*4+3]=sb.w;
    __syncthreads();
    for(int idx=threadIdx.x; idx<384; idx+=256){
        float s=0.f;
        #pragma unroll
        for(int w=0;w<8;w++) s += sP[w][idx];
        g_partS[blockIdx.x*768 + idx] = s;
    }
    __syncthreads();
    // round 2: sb2, su, sx
    sP[warp][lane*4+0]=sb2.x; sP[warp][lane*4+1]=sb2.y; sP[warp][lane*4+2]=sb2.z; sP[warp][lane*4+3]=sb2.w;
    sP[warp][128+lane*4+0]=su.x; sP[warp][128+lane*4+1]=su.y; sP[warp][128+lane*4+2]=su.z; sP[warp][128+lane*4+3]=su.w;
    sP[warp][256+lane*4+0]=sx.x; sP[warp][256+lane*4+1]=sx.y; sP[warp][256+lane*4+2]=sx.z; sP[warp][256+lane*4+3]=sx.w;
    __syncthreads();
    for(int idx=threadIdx.x; idx<384; idx+=256){
        float s=0.f;
        #pragma unroll
        for(int w=0;w<8;w++) s += sP[w][idx];
        g_partS[blockIdx.x*768 + 384 + idx] = s;
    }
}

__global__ void k_fold1(const float* __restrict__ Wc, const float* __restrict__ g1,
                        const float* __restrict__ b1){
    __shared__ float sW[EFL][128];
    for(int i=threadIdx.x;i<EFL*C2;i+=128){
        int k = i>>7, c = i&127;
        sW[k][c] = Wc[(C2+k)*C2 + c];
    }
    __syncthreads();
    int t = threadIdx.x;   // 128
    float Sa=0,Sa2=0,Sb=0,Sb2=0,Su=0,Sx=0;
    for(int b=0;b<GRID_S;b++){
        int base = b*768;
        Sa  += g_partS[base+t];     Sa2 += g_partS[base+128+t];
        Sb  += g_partS[base+256+t]; Sb2 += g_partS[base+384+t];
        Su  += g_partS[base+512+t]; Sx  += g_partS[base+640+t];
    }
    float Hterm = 0.f;
    for(int k=0;k<EFL;k++){
        int lo = max(0,k-7), hi = min(EFL-1,k+7);
        for(int k2=lo;k2<=hi;k2++){
            unsigned long long hv = g_HU[k*EFL+k2];
            if(hv){
                float Hf = (float)((double)hv * (1.0/1073741824.0));
                Hterm = fmaf(Hf*sW[k][t], sW[k2][t], Hterm);
            }
        }
    }
    float sz  = 12.f*Sa  + Sb  + Su;
    float sz2 = 12.f*Sa2 + Sb2 + Hterm + 2.f*Sx;
    const float inv = 1.0f/(float)NEDGE;
    float mean = sz*inv;
    float var  = sz2*inv - mean*mean;
    float sc = g1[t] * rsqrtf(var + EPSF);
    g_scale1[t] = sc;
    g_shift1[t] = b1[t] - mean*sc;
}

// ---------------- fused edge pass: z (regs) -> BN1 -> gate -> nbr-sum -> BN2 partials ----------------
__global__ __launch_bounds__(256) void k_act(const float* __restrict__ Wc,
                                             const float* __restrict__ bias,
                                             const int* __restrict__ nidx,
                                             const float* __restrict__ nd){
    __shared__ __align__(16) float sWe[EFL][132];
    __shared__ float sP2[8][128];
    for(int i=threadIdx.x;i<EFL*C2;i+=256){
        int k = i>>7, c = i&127;
        sWe[k][c] = Wc[(C2+k)*C2 + c];
    }
    __syncthreads();
    const int warp = threadIdx.x>>5, lane = threadIdx.x&31;
    float4 bb  = *(const float4*)&bias[lane*4];
    float4 sc1 = *(const float4*)&g_scale1[lane*4];
    float4 sh1 = *(const float4*)&g_shift1[lane*4];
    float4 s2 = make_float4(0,0,0,0), q2 = s2;
    for(int n = blockIdx.x*8 + warp; n < NATOMS; n += GRID_A*8){
        float4 xs = *(const float4*)&g_xW[n*(2*C2) + lane*4];
        xs.x += bb.x; xs.y += bb.y; xs.z += bb.z; xs.w += bb.w;
        int myi = 0; float myd = 0.f;
        if(lane < MM){ myi = nidx[n*MM + lane]; myd = nd[n*MM + lane]; }
        float4 acc = make_float4(0,0,0,0);
        #pragma unroll 1
        for(int m=0;m<MM;m++){
            int   j = __shfl_sync(FULLM, myi, m);
            float d = __shfl_sync(FULLM, myd, m);
            int kc = __float2int_rn(d*5.0f);
            int ks = min(max(kc-3,0), EFL-8);
            float uu = d - STEPF*(float)(ks+lane);
            float gl = expf(-uu*uu*25.0f);
            float4 xn = *(const float4*)&g_xW[j*(2*C2) + C2 + lane*4];
            float4 c4 = make_float4(0,0,0,0);
            #pragma unroll
            for(int t=0;t<8;t++){
                float g = __shfl_sync(FULLM, gl, t);
                float4 wv = *(const float4*)&sWe[ks+t][lane*4];
                FMA4(c4, g, wv);
            }
            float4 z;
            z.x = xs.x + xn.x + c4.x;
            z.y = xs.y + xn.y + c4.y;
            z.z = xs.z + xn.z + c4.z;
            z.w = xs.w + xn.w + c4.w;
            float4 f;
            f.x = fmaf(z.x, sc1.x, sh1.x);
            f.y = fmaf(z.y, sc1.y, sh1.y);
            f.z = fmaf(z.z, sc1.z, sh1.z);
            f.w = fmaf(z.w, sc1.w, sh1.w);
            float4 val;
            if(lane < 16){
                val.x = sigf(f.x); val.y = sigf(f.y); val.z = sigf(f.z); val.w = sigf(f.w);
            } else {
                val.x = spf(f.x);  val.y = spf(f.y);  val.z = spf(f.z);  val.w = spf(f.w);
            }
            float4 par;
            par.x = __shfl_xor_sync(FULLM, val.x, 16);
            par.y = __shfl_xor_sync(FULLM, val.y, 16);
            par.z = __shfl_xor_sync(FULLM, val.z, 16);
            par.w = __shfl_xor_sync(FULLM, val.w, 16);
            acc.x = fmaf(val.x, par.x, acc.x);
            acc.y = fmaf(val.y, par.y, acc.y);
            acc.z = fmaf(val.z, par.z, acc.z);
            acc.w = fmaf(val.w, par.w, acc.w);
        }
        if(lane < 16){
            *(float4*)&g_summed[n*AFL + lane*4] = acc;
            ADD4(s2, acc);
            q2.x = fmaf(acc.x,acc.x,q2.x); q2.y = fmaf(acc.y,acc.y,q2.y);
            q2.z = fmaf(acc.z,acc.z,q2.z); q2.w = fmaf(acc.w,acc.w,q2.w);
        }
    }
    if(lane < 16){
        sP2[warp][lane*4+0] = s2.x; sP2[warp][lane*4+1] = s2.y;
        sP2[warp][lane*4+2] = s2.z; sP2[warp][lane*4+3] = s2.w;
        sP2[warp][64+lane*4+0] = q2.x; sP2[warp][64+lane*4+1] = q2.y;
        sP2[warp][64+lane*4+2] = q2.z; sP2[warp][64+lane*4+3] = q2.w;
    }
    __syncthreads();
    int t = threadIdx.x;
    if(t < 128){
        float s = 0.f;
        #pragma unroll
        for(int w=0;w<8;w++) s += sP2[w][t];
        g_part2[blockIdx.x*128 + t] = s;
    }
}

__global__ void k_fold2(const float* __restrict__ g2, const float* __restrict__ b2){
    int t = threadIdx.x;   // 64
    float s = 0.f, q = 0.f;
    for(int b=0;b<GRID_A;b++){ s += g_part2[b*128+t]; q += g_part2[b*128+64+t]; }
    const float inv = 1.0f/(float)NATOMS;
    float mean = s*inv;
    float var  = q*inv - mean*mean;
    float sc = g2[t] * rsqrtf(var + EPSF);
    g_scale2[t] = sc;
    g_shift2[t] = b2[t] - mean*sc;
}

__global__ void k_update(){
    int i = blockIdx.x*blockDim.x + threadIdx.x;
    if(i < NATOMS*AFL){
        int c = i & (AFL-1);
        float v = g_x[i] + fmaf(g_summed[i], g_scale2[c], g_shift2[c]);
        g_x[i] = fmaxf(v,0.f) + log1pf(expf(-fabsf(v)));
    }
}

// ---------------- pooling + MLP head ----------------
__global__ void k_pool(const int* __restrict__ cnt, const float* __restrict__ fcW,
                       const float* __restrict__ fcb, const float* __restrict__ foW,
                       const float* __restrict__ fob, float* __restrict__ out){
    const int cid = blockIdx.x, t = threadIdx.x, w = t>>5, l = t&31;
    __shared__ float sm[AFL];
    __shared__ int sip[4];
    __shared__ float sfp[4];
    int part = 0;
    for(int i=t; i<cid; i+=128) part += cnt[i];
    for(int o=16;o;o>>=1) part += __shfl_down_sync(FULLM, part, o);
    if(l==0) sip[w] = part;
    __syncthreads();
    const int off = sip[0]+sip[1]+sip[2]+sip[3];
    const int c = cnt[cid];
    if(t < AFL){
        float s = 0.f;
        for(int a=0;a<c;a++) s += g_x[(off+a)*AFL + t];
        float v = s/(float)c;
        sm[t] = fmaxf(v,0.f) + log1pf(expf(-fabsf(v)));
    }
    __syncthreads();
    float h = fcb[t];
    for(int k=0;k<AFL;k++) h = fmaf(sm[k], fcW[k*HFL + t], h);
    h = fmaxf(h,0.f) + log1pf(expf(-fabsf(h)));
    float v = h * foW[t];
    for(int o=16;o;o>>=1) v += __shfl_down_sync(FULLM, v, o);
    if(l==0) sfp[w] = v;
    __syncthreads();
    if(t==0) out[cid] = sfp[0]+sfp[1]+sfp[2]+sfp[3] + fob[0];
}

// ---------------- launch ----------------
extern "C" void kernel_launch(void* const* d_in, const int* in_sizes, int n_in,
                              void* d_out, int out_size){
    const int*   atom_fea   = (const int*)  d_in[0];
    const float* nbr_fea    = (const float*)d_in[1];
    const int*   nbr_idx    = (const int*)  d_in[2];
    const int*   cnt        = (const int*)  d_in[3];
    const float* atom_table = (const float*)d_in[4];
    const float* W_embed    = (const float*)d_in[5];
    const float* W_conv     = (const float*)d_in[6];
    const float* b_conv     = (const float*)d_in[7];
    const float* bn1_g      = (const float*)d_in[8];
    const float* bn1_b      = (const float*)d_in[9];
    const float* bn2_g      = (const float*)d_in[10];
    const float* bn2_b      = (const float*)d_in[11];
    const float* fc_W       = (const float*)d_in[12];
    const float* fc_b       = (const float*)d_in[13];
    const float* fo_W       = (const float*)d_in[14];
    const float* fo_b       = (const float*)d_in[15];
    float* out = (float*)d_out;

    k_zero<<<2048, 256>>>();
    k_prep<<<GRID_P, 256>>>(nbr_idx, nbr_fea);
    k_embed<<<NTYPES, AFL>>>(atom_table, W_embed);
    k_gatherx<<<(NATOMS*AFL + 255)/256, 256>>>(atom_fea);

    for(int l=0;l<NCONV;l++){
        const float* W = W_conv + l*(2*AFL+EFL)*C2;
        k_gemm<<<dim3(296,2), 256>>>(W);
        k_stats<<<GRID_S, 256>>>(W, b_conv + l*C2, nbr_idx);
        k_fold1<<<1, 128>>>(W, bn1_g + l*C2, bn1_b + l*C2);
        k_act<<<GRID_A, 256>>>(W, b_conv + l*C2, nbr_idx, nbr_fea);
        k_fold2<<<1, 64>>>(bn2_g + l*AFL, bn2_b + l*AFL);
        k_update<<<(NATOMS*AFL + 255)/256, 256>>>();
    }
    k_pool<<<NCRYS, 128>>>(cnt, fc_W, fc_b, fo_W, fo_b, out);
}

// round 6
// speedup vs baseline: 1.6811x; 1.6811x over previous
#include <cuda_runtime.h>
#include <cuda_fp16.h>
#include <math.h>

#define NATOMS 120000
#define MM 12
#define AFL 64
#define EFL 41
#define C2 128
#define NCONV 3
#define NCRYS 2400
#define ORIG 92
#define NTYPES 100
#define HFL 128
#define GRIDN 592
#define STEPF 0.2f
#define EPSF 1e-5f
#define NEDGE (NATOMS*MM)
#define FULLM 0xffffffffu
#define TABN 768          // bins on [0,12], 1/64 per bin

// ---------------- device scratch ----------------
__device__ float  g_embed[NTYPES*AFL];
__device__ float  g_x[NATOMS*AFL];
__device__ float  g_xWs[NATOMS*C2];                       // self half, fp32 (streamed)
__device__ __align__(16) __half g_xWn[NATOMS*C2];         // nbr half, fp16 (gathered, 30MB -> L2)
__device__ __align__(16) __half g_zh[NEDGE*C2];           // z scratch fp16 (368MB)
__device__ float  g_summed[NATOMS*AFL];
__device__ float  g_part1[GRIDN*256];
__device__ float  g_part2[GRIDN*128];
__device__ float  g_scale1[C2], g_shift1[C2], g_scale2[AFL], g_shift2[AFL];
__device__ float2 g_tsig[TABN+2];   // (value, next-value delta) of sigmoid(|x|)
__device__ float2 g_ttail[TABN+2];  // softplus tail ln(1+e^-|x|)

#define FMA4(Zv,Gv,Wv) { (Zv).x=fmaf((Gv),(Wv).x,(Zv).x); (Zv).y=fmaf((Gv),(Wv).y,(Zv).y); (Zv).z=fmaf((Gv),(Wv).z,(Zv).z); (Zv).w=fmaf((Gv),(Wv).w,(Zv).w); }

// ---------------- activation tables (built once) ----------------
__global__ void k_tab(){
    int i = blockIdx.x*blockDim.x + threadIdx.x;
    if(i <= TABN){
        float u0 = (float)i/64.f, u1 = (float)(i+1)/64.f;
        float s0 = 1.f/(1.f+expf(-u0)), s1 = 1.f/(1.f+expf(-u1));
        float t0 = log1pf(expf(-u0)),  t1 = log1pf(expf(-u1));
        g_tsig[i]  = make_float2(s0, s1-s0);
        g_ttail[i] = make_float2(t0, t1-t0);
    }
}

// ---------------- embed table: atom_table @ W_embed ----------------
__global__ void k_embed(const float* __restrict__ at, const float* __restrict__ we){
    int t = blockIdx.x, c = threadIdx.x;
    float s = 0.f;
    for(int o=0;o<ORIG;o++) s = fmaf(at[t*ORIG+o], we[o*AFL+c], s);
    g_embed[t*AFL+c] = s;
}

__global__ void k_gatherx(const int* __restrict__ af){
    int i = blockIdx.x*blockDim.x + threadIdx.x;
    if(i < NATOMS*AFL){
        int n = i >> 6, c = i & 63;
        g_x[i] = g_embed[af[n]*AFL + c];
    }
}

// ---------------- xW gemm: [N,64] @ [64,256] -> self fp32 / nbr fp16 ----------------
__global__ void k_gemm(const float* __restrict__ W){
    __shared__ __align__(16) float sW[64][132];
    __shared__ float sX[32][65];
    const int half = blockIdx.y;   // 0 self -> g_xWs, 1 nbr -> g_xWn fp16
    for(int i=threadIdx.x;i<64*C2;i+=256){
        int k = i >> 7, c = i & 127;
        sW[k][c] = W[(half*AFL + k)*C2 + c];
    }
    const int tx = threadIdx.x & 31;
    const int ty = threadIdx.x >> 5;
    for(int tile=blockIdx.x; tile < NATOMS/32; tile += gridDim.x){
        const int row0 = tile*32;
        __syncthreads();
        for(int i=threadIdx.x;i<32*AFL;i+=256){
            int r = i >> 6, k = i & 63;
            sX[r][k] = g_x[(row0+r)*AFL + k];
        }
        __syncthreads();
        float acc[4][4];
        #pragma unroll
        for(int r=0;r<4;r++){
            #pragma unroll
            for(int c=0;c<4;c++) acc[r][c]=0.f;
        }
        #pragma unroll
        for(int k=0;k<AFL;k++){
            float4 wv = *(const float4*)&sW[k][tx*4];
            #pragma unroll
            for(int r=0;r<4;r++){
                float xv = sX[ty*4+r][k];
                acc[r][0] = fmaf(xv, wv.x, acc[r][0]);
                acc[r][1] = fmaf(xv, wv.y, acc[r][1]);
                acc[r][2] = fmaf(xv, wv.z, acc[r][2]);
                acc[r][3] = fmaf(xv, wv.w, acc[r][3]);
            }
        }
        #pragma unroll
        for(int r=0;r<4;r++){
            int row = row0 + ty*4 + r;
            if(half==0){
                *(float4*)&g_xWs[row*C2 + tx*4] =
                    make_float4(acc[r][0],acc[r][1],acc[r][2],acc[r][3]);
            } else {
                __half2 h[2];
                h[0] = __float22half2_rn(make_float2(acc[r][0],acc[r][1]));
                h[1] = __float22half2_rn(make_float2(acc[r][2],acc[r][3]));
                *(uint2*)&g_xWn[row*C2 + tx*4] = *(uint2*)h;
            }
        }
    }
}

// ---------------- pass1: z = xs + gather(xn fp16) + gauss@We + b -> fp16 store + stats ----------------
__global__ __launch_bounds__(256) void k_pass1(const float* __restrict__ Wc,
                                               const float* __restrict__ bias,
                                               const int* __restrict__ nidx,
                                               const float* __restrict__ nd){
    __shared__ __align__(16) float sWe[EFL][132];
    __shared__ float sPart[8][256];
    for(int i=threadIdx.x;i<EFL*C2;i+=256){
        int k = i>>7, c = i&127;
        sWe[k][c] = Wc[(C2+k)*C2 + c];
    }
    __syncthreads();
    const int warp = threadIdx.x >> 5, lane = threadIdx.x & 31;
    float4 bb = *(const float4*)&bias[lane*4];
    float4 s4 = make_float4(0,0,0,0), q4 = s4;
    for(int n = blockIdx.x*8 + warp; n < NATOMS; n += GRIDN*8){
        float4 xs = *(const float4*)&g_xWs[n*C2 + lane*4];
        xs.x += bb.x; xs.y += bb.y; xs.z += bb.z; xs.w += bb.w;
        int myi = 0; float myd = 0.f;
        if(lane < MM){ myi = nidx[n*MM + lane]; myd = nd[n*MM + lane]; }
        #pragma unroll 1
        for(int m=0;m<MM;m++){
            int   j = __shfl_sync(FULLM, myi, m);
            float d = __shfl_sync(FULLM, myd, m);
            int kc = __float2int_rn(d*5.0f);
            int ks = min(max(kc-3,0), EFL-8);
            float uu = d - STEPF*(float)(ks+lane);
            float gl = __expf(-uu*uu*25.0f);
            uint2 hv = *(const uint2*)&g_xWn[j*C2 + lane*4];
            __half2* hp = (__half2*)&hv;
            float2 xlo = __half22float2(hp[0]);
            float2 xhi = __half22float2(hp[1]);
            float4 z;
            z.x = xs.x + xlo.x; z.y = xs.y + xlo.y;
            z.z = xs.z + xhi.x; z.w = xs.w + xhi.y;
            #pragma unroll
            for(int t=0;t<8;t++){
                float g = __shfl_sync(FULLM, gl, t);
                float4 wv = *(const float4*)&sWe[ks+t][lane*4];
                FMA4(z, g, wv);
            }
            // round to fp16, store, accumulate stats on ROUNDED values (self-consistent BN)
            __half2 zh[2];
            zh[0] = __float22half2_rn(make_float2(z.x, z.y));
            zh[1] = __float22half2_rn(make_float2(z.z, z.w));
            *(uint2*)&g_zh[(n*MM + m)*C2 + lane*4] = *(uint2*)zh;
            float2 r0 = __half22float2(zh[0]);
            float2 r1 = __half22float2(zh[1]);
            s4.x += r0.x; s4.y += r0.y; s4.z += r1.x; s4.w += r1.y;
            q4.x = fmaf(r0.x,r0.x,q4.x); q4.y = fmaf(r0.y,r0.y,q4.y);
            q4.z = fmaf(r1.x,r1.x,q4.z); q4.w = fmaf(r1.y,r1.y,q4.w);
        }
    }
    sPart[warp][lane*4+0]=s4.x; sPart[warp][lane*4+1]=s4.y;
    sPart[warp][lane*4+2]=s4.z; sPart[warp][lane*4+3]=s4.w;
    sPart[warp][128+lane*4+0]=q4.x; sPart[warp][128+lane*4+1]=q4.y;
    sPart[warp][128+lane*4+2]=q4.z; sPart[warp][128+lane*4+3]=q4.w;
    __syncthreads();
    int t = threadIdx.x;
    float s = 0.f;
    #pragma unroll
    for(int w=0;w<8;w++) s += sPart[w][t];
    g_part1[blockIdx.x*256 + t] = s;
}

__global__ void k_fold1(const float* __restrict__ g1, const float* __restrict__ b1){
    int t = threadIdx.x;   // 128
    float s = 0.f, q = 0.f;
    for(int b=0;b<GRIDN;b++){ s += g_part1[b*256+t]; q += g_part1[b*256+128+t]; }
    const float inv = 1.0f/(float)NEDGE;
    float mean = s*inv;
    float var  = q*inv - mean*mean;
    float sc = g1[t] * rsqrtf(var + EPSF);
    g_scale1[t] = sc;
    g_shift1[t] = b1[t] - mean*sc;
}

// ---------------- pass2: fp16 z read -> BN1 -> table gate -> nbr-sum -> stats ----------------
__global__ __launch_bounds__(256) void k_pass2(){
    __shared__ float sc[C2], sh[C2];
    __shared__ float2 sTs[TABN+2], sTt[TABN+2];
    __shared__ float sPart[8][128];
    if(threadIdx.x < C2){ sc[threadIdx.x] = g_scale1[threadIdx.x]; sh[threadIdx.x] = g_shift1[threadIdx.x]; }
    for(int i=threadIdx.x;i<=TABN;i+=256){ sTs[i] = g_tsig[i]; sTt[i] = g_ttail[i]; }
    __syncthreads();
    const int warp = threadIdx.x >> 5, lane = threadIdx.x & 31;
    const int c0 = lane*2;
    float scf0 = sc[c0], scf1 = sc[c0+1], shf0 = sh[c0], shf1 = sh[c0+1];
    float scc0 = sc[AFL+c0], scc1 = sc[AFL+c0+1], shc0 = sh[AFL+c0], shc1 = sh[AFL+c0+1];
    float s0=0.f,s1=0.f,q0=0.f,q1=0.f;
    for(int n = blockIdx.x*8 + warp; n < NATOMS; n += GRIDN*8){
        float a0=0.f, a1=0.f;
        #pragma unroll 1
        for(int m=0;m<MM;m++){
            const __half* ez = &g_zh[(n*MM + m)*C2];
            float2 zf = __half22float2(*(const __half2*)&ez[c0]);
            float2 zc = __half22float2(*(const __half2*)&ez[AFL + c0]);
            float f0 = fmaf(zf.x, scf0, shf0);
            float f1 = fmaf(zf.y, scf1, shf1);
            float h0 = fmaf(zc.x, scc0, shc0);
            float h1 = fmaf(zc.y, scc1, shc1);
            // sigmoid via table on |f|
            float af0 = fminf(fabsf(f0)*64.f, (float)(TABN-1));
            float af1 = fminf(fabsf(f1)*64.f, (float)(TABN-1));
            int i0 = (int)af0, i1 = (int)af1;
            float2 e0 = sTs[i0], e1 = sTs[i1];
            float sg0 = fmaf(af0-(float)i0, e0.y, e0.x);
            float sg1 = fmaf(af1-(float)i1, e1.y, e1.x);
            sg0 = (f0 < 0.f) ? 1.f - sg0 : sg0;
            sg1 = (f1 < 0.f) ? 1.f - sg1 : sg1;
            // softplus = max(h,0) + tail(|h|)
            float ah0 = fminf(fabsf(h0)*64.f, (float)(TABN-1));
            float ah1 = fminf(fabsf(h1)*64.f, (float)(TABN-1));
            int j0 = (int)ah0, j1 = (int)ah1;
            float2 t0 = sTt[j0], t1 = sTt[j1];
            float sp0 = fmaxf(h0,0.f) + fmaf(ah0-(float)j0, t0.y, t0.x);
            float sp1 = fmaxf(h1,0.f) + fmaf(ah1-(float)j1, t1.y, t1.x);
            a0 = fmaf(sg0, sp0, a0);
            a1 = fmaf(sg1, sp1, a1);
        }
        *(float2*)&g_summed[n*AFL + c0] = make_float2(a0, a1);
        s0 += a0; s1 += a1;
        q0 = fmaf(a0,a0,q0); q1 = fmaf(a1,a1,q1);
    }
    sPart[warp][c0]   = s0; sPart[warp][c0+1]   = s1;
    sPart[warp][AFL+c0] = q0; sPart[warp][AFL+c0+1] = q1;
    __syncthreads();
    int t = threadIdx.x;
    if(t < 128){
        float s = 0.f;
        #pragma unroll
        for(int w=0;w<8;w++) s += sPart[w][t];
        g_part2[blockIdx.x*128 + t] = s;
    }
}

__global__ void k_fold2(const float* __restrict__ g2, const float* __restrict__ b2){
    int t = threadIdx.x;   // 64
    float s = 0.f, q = 0.f;
    for(int b=0;b<GRIDN;b++){ s += g_part2[b*128+t]; q += g_part2[b*128+64+t]; }
    const float inv = 1.0f/(float)NATOMS;
    float mean = s*inv;
    float var  = q*inv - mean*mean;
    float sc = g2[t] * rsqrtf(var + EPSF);
    g_scale2[t] = sc;
    g_shift2[t] = b2[t] - mean*sc;
}

__global__ void k_update(){
    int i = blockIdx.x*blockDim.x + threadIdx.x;
    if(i < NATOMS*AFL){
        int c = i & (AFL-1);
        float v = g_x[i] + fmaf(g_summed[i], g_scale2[c], g_shift2[c]);
        g_x[i] = fmaxf(v,0.f) + log1pf(expf(-fabsf(v)));
    }
}

// ---------------- pooling + MLP head ----------------
__global__ void k_pool(const int* __restrict__ cnt, const float* __restrict__ fcW,
                       const float* __restrict__ fcb, const float* __restrict__ foW,
                       const float* __restrict__ fob, float* __restrict__ out){
    const int cid = blockIdx.x, t = threadIdx.x, w = t>>5, l = t&31;
    __shared__ float sm[AFL];
    __shared__ int sip[4];
    __shared__ float sfp[4];
    int part = 0;
    for(int i=t; i<cid; i+=128) part += cnt[i];
    for(int o=16;o;o>>=1) part += __shfl_down_sync(FULLM, part, o);
    if(l==0) sip[w] = part;
    __syncthreads();
    const int off = sip[0]+sip[1]+sip[2]+sip[3];
    const int c = cnt[cid];
    if(t < AFL){
        float s = 0.f;
        for(int a=0;a<c;a++) s += g_x[(off+a)*AFL + t];
        float v = s/(float)c;
        sm[t] = fmaxf(v,0.f) + log1pf(expf(-fabsf(v)));
    }
    __syncthreads();
    float h = fcb[t];
    for(int k=0;k<AFL;k++) h = fmaf(sm[k], fcW[k*HFL + t], h);
    h = fmaxf(h,0.f) + log1pf(expf(-fabsf(h)));
    float v = h * foW[t];
    for(int o=16;o;o>>=1) v += __shfl_down_sync(FULLM, v, o);
    if(l==0) sfp[w] = v;
    __syncthreads();
    if(t==0) out[cid] = sfp[0]+sfp[1]+sfp[2]+sfp[3] + fob[0];
}

// ---------------- launch ----------------
extern "C" void kernel_launch(void* const* d_in, const int* in_sizes, int n_in,
                              void* d_out, int out_size){
    const int*   atom_fea   = (const int*)  d_in[0];
    const float* nbr_fea    = (const float*)d_in[1];
    const int*   nbr_idx    = (const int*)  d_in[2];
    const int*   cnt        = (const int*)  d_in[3];
    const float* atom_table = (const float*)d_in[4];
    const float* W_embed    = (const float*)d_in[5];
    const float* W_conv     = (const float*)d_in[6];
    const float* b_conv     = (const float*)d_in[7];
    const float* bn1_g      = (const float*)d_in[8];
    const float* bn1_b      = (const float*)d_in[9];
    const float* bn2_g      = (const float*)d_in[10];
    const float* bn2_b      = (const float*)d_in[11];
    const float* fc_W       = (const float*)d_in[12];
    const float* fc_b       = (const float*)d_in[13];
    const float* fo_W       = (const float*)d_in[14];
    const float* fo_b       = (const float*)d_in[15];
    float* out = (float*)d_out;

    k_tab<<<4, 256>>>();
    k_embed<<<NTYPES, AFL>>>(atom_table, W_embed);
    k_gatherx<<<(NATOMS*AFL + 255)/256, 256>>>(atom_fea);

    for(int l=0;l<NCONV;l++){
        const float* W = W_conv + l*(2*AFL+EFL)*C2;
        k_gemm<<<dim3(296,2), 256>>>(W);
        k_pass1<<<GRIDN, 256>>>(W, b_conv + l*C2, nbr_idx, nbr_fea);
        k_fold1<<<1, 128>>>(bn1_g + l*C2, bn1_b + l*C2);
        k_pass2<<<GRIDN, 256>>>();
        k_fold2<<<1, 64>>>(bn2_g + l*AFL, bn2_b + l*AFL);
        k_update<<<(NATOMS*AFL + 255)/256, 256>>>();
    }
    k_pool<<<NCRYS, 128>>>(cnt, fc_W, fc_b, fo_W, fo_b, out);
}

// round 7
// speedup vs baseline: 1.9107x; 1.1366x over previous
#include <cuda_runtime.h>
#include <cuda_fp16.h>
#include <math.h>

#define NATOMS 120000
#define MM 12
#define AFL 64
#define EFL 41
#define C2 128
#define NCONV 3
#define NCRYS 2400
#define ORIG 92
#define NTYPES 100
#define HFL 128
#define GRIDN 592
#define STEPF 0.2f
#define EPSF 1e-5f
#define NEDGE (NATOMS*MM)
#define FULLM 0xffffffffu
#define TABN 768          // activation LUT bins on [0,12], 1/64 per bin
#define DBINS 1024        // distance bins over [0,8), 1/128 per bin

// ---------------- device scratch ----------------
__device__ float  g_embed[NTYPES*AFL];
__device__ float  g_x[NATOMS*AFL];
__device__ float  g_xWs[NATOMS*C2];                       // self half, fp32 (streamed)
__device__ __align__(16) __half g_xWn[NATOMS*C2];         // nbr half, fp16 (30MB, L2)
__device__ __align__(16) __half g_zh[NEDGE*C2];           // z scratch fp16 (368MB)
__device__ __align__(16) __half2 g_ctab[DBINS*C2];        // edge-term table (v_b, v_{b+1})
__device__ float  g_summed[NATOMS*AFL];
__device__ float  g_part1[GRIDN*256];
__device__ float  g_part2[GRIDN*128];
__device__ float  g_scale1[C2], g_shift1[C2], g_scale2[AFL], g_shift2[AFL];
__device__ float2 g_tsig[TABN+2];
__device__ float2 g_ttail[TABN+2];

// ---------------- activation tables (built once) ----------------
__global__ void k_tab(){
    int i = blockIdx.x*blockDim.x + threadIdx.x;
    if(i <= TABN){
        float u0 = (float)i/64.f, u1 = (float)(i+1)/64.f;
        float s0 = 1.f/(1.f+expf(-u0)), s1 = 1.f/(1.f+expf(-u1));
        float t0 = log1pf(expf(-u0)),  t1 = log1pf(expf(-u1));
        g_tsig[i]  = make_float2(s0, s1-s0);
        g_ttail[i] = make_float2(t0, t1-t0);
    }
}

// ---------------- edge-term table: ctab[b,:] = sum_t gauss_t(b/128) * We[t,:] ----------------
__global__ void k_ctab(const float* __restrict__ Wc){
    __shared__ float sWe[EFL][C2];
    for(int i=threadIdx.x;i<EFL*C2;i+=128){
        sWe[i>>7][i&127] = Wc[(C2+(i>>7))*C2 + (i&127)];
    }
    __syncthreads();
    int b = blockIdx.x;      // 0..1023
    int c = threadIdx.x;     // 0..127
    float d0 = (float)b * (1.f/128.f);
    float d1 = (float)(b+1) * (1.f/128.f);
    int t0 = max(0, (int)(d0*5.f) - 4);
    float v0 = 0.f, v1 = 0.f;
    #pragma unroll
    for(int dt=0; dt<10; dt++){
        int t = t0 + dt;
        if(t < EFL){
            float w = sWe[t][c];
            float u0 = d0 - STEPF*(float)t;
            float u1 = d1 - STEPF*(float)t;
            v0 = fmaf(expf(-u0*u0*25.f), w, v0);
            v1 = fmaf(expf(-u1*u1*25.f), w, v1);
        }
    }
    g_ctab[b*C2 + c] = __halves2half2(__float2half_rn(v0), __float2half_rn(v1));
}

// ---------------- embed table: atom_table @ W_embed ----------------
__global__ void k_embed(const float* __restrict__ at, const float* __restrict__ we){
    int t = blockIdx.x, c = threadIdx.x;
    float s = 0.f;
    for(int o=0;o<ORIG;o++) s = fmaf(at[t*ORIG+o], we[o*AFL+c], s);
    g_embed[t*AFL+c] = s;
}

__global__ void k_gatherx(const int* __restrict__ af){
    int i = blockIdx.x*blockDim.x + threadIdx.x;
    if(i < NATOMS*AFL){
        int n = i >> 6, c = i & 63;
        g_x[i] = g_embed[af[n]*AFL + c];
    }
}

// ---------------- xW gemm: [N,64]@[64,256], transposed x tile, 4x4/thread ----------------
__global__ __launch_bounds__(256) void k_gemm(const float* __restrict__ W){
    __shared__ float sW[64][C2];          // 32.8 KB
    __shared__ float sXT[64][36];         // 9.2 KB, [k][row], padded for float4
    const int half = blockIdx.y;          // 0 self -> fp32, 1 nbr -> fp16
    const int cg = threadIdx.x & 31;      // cols cg*4
    const int rg = threadIdx.x >> 5;      // rows rg*4 (0..7 -> 32 rows)
    for(int i=threadIdx.x;i<64*C2;i+=256){
        sW[i>>7][i&127] = W[(half*AFL + (i>>7))*C2 + (i&127)];
    }
    for(int tile=blockIdx.x; tile < NATOMS/32; tile += gridDim.x){
        const int row0 = tile*32;
        __syncthreads();
        for(int i=threadIdx.x;i<32*AFL;i+=256){
            int r = i >> 6, k = i & 63;
            sXT[k][r] = g_x[(row0+r)*AFL + k];
        }
        __syncthreads();
        float acc[4][4];
        #pragma unroll
        for(int r=0;r<4;r++){
            #pragma unroll
            for(int c=0;c<4;c++) acc[r][c]=0.f;
        }
        #pragma unroll
        for(int k=0;k<AFL;k++){
            float4 xv = *(const float4*)&sXT[k][rg*4];
            float4 wv = *(const float4*)&sW[k][cg*4];
            acc[0][0]=fmaf(xv.x,wv.x,acc[0][0]); acc[0][1]=fmaf(xv.x,wv.y,acc[0][1]);
            acc[0][2]=fmaf(xv.x,wv.z,acc[0][2]); acc[0][3]=fmaf(xv.x,wv.w,acc[0][3]);
            acc[1][0]=fmaf(xv.y,wv.x,acc[1][0]); acc[1][1]=fmaf(xv.y,wv.y,acc[1][1]);
            acc[1][2]=fmaf(xv.y,wv.z,acc[1][2]); acc[1][3]=fmaf(xv.y,wv.w,acc[1][3]);
            acc[2][0]=fmaf(xv.z,wv.x,acc[2][0]); acc[2][1]=fmaf(xv.z,wv.y,acc[2][1]);
            acc[2][2]=fmaf(xv.z,wv.z,acc[2][2]); acc[2][3]=fmaf(xv.z,wv.w,acc[2][3]);
            acc[3][0]=fmaf(xv.w,wv.x,acc[3][0]); acc[3][1]=fmaf(xv.w,wv.y,acc[3][1]);
            acc[3][2]=fmaf(xv.w,wv.z,acc[3][2]); acc[3][3]=fmaf(xv.w,wv.w,acc[3][3]);
        }
        #pragma unroll
        for(int r=0;r<4;r++){
            int row = row0 + rg*4 + r;
            if(half==0){
                *(float4*)&g_xWs[row*C2 + cg*4] =
                    make_float4(acc[r][0],acc[r][1],acc[r][2],acc[r][3]);
            } else {
                __half2 h[2];
                h[0] = __float22half2_rn(make_float2(acc[r][0],acc[r][1]));
                h[1] = __float22half2_rn(make_float2(acc[r][2],acc[r][3]));
                *(uint2*)&g_xWn[row*C2 + cg*4] = *(uint2*)h;
            }
        }
    }
}

// ---------------- pass1: z = xs+b + gather(xn fp16) + ctab lerp -> fp16 store + stats ----------------
__global__ __launch_bounds__(256) void k_pass1(const float* __restrict__ bias,
                                               const int* __restrict__ nidx,
                                               const float* __restrict__ nd){
    __shared__ float sPart[8][256];
    const int warp = threadIdx.x >> 5, lane = threadIdx.x & 31;
    float4 bb = *(const float4*)&bias[lane*4];
    float4 s4 = make_float4(0,0,0,0), q4 = s4;
    for(int n = blockIdx.x*8 + warp; n < NATOMS; n += GRIDN*8){
        float4 xs = *(const float4*)&g_xWs[n*C2 + lane*4];
        xs.x += bb.x; xs.y += bb.y; xs.z += bb.z; xs.w += bb.w;
        int myi = 0; float myd = 0.f;
        if(lane < MM){ myi = nidx[n*MM + lane]; myd = nd[n*MM + lane]; }
        #pragma unroll 1
        for(int m=0;m<MM;m++){
            int   j = __shfl_sync(FULLM, myi, m);
            float d = __shfl_sync(FULLM, myd, m);
            float db = d * 128.f;
            int bin = min((int)db, DBINS-1);
            float frac = db - (float)bin;
            uint4 tv = *(const uint4*)&g_ctab[bin*C2 + lane*4];
            __half2* tp = (__half2*)&tv;
            uint2 hv = *(const uint2*)&g_xWn[j*C2 + lane*4];
            __half2* hp = (__half2*)&hv;
            float2 xlo = __half22float2(hp[0]);
            float2 xhi = __half22float2(hp[1]);
            float2 c0 = __half22float2(tp[0]);
            float2 c1 = __half22float2(tp[1]);
            float2 c2 = __half22float2(tp[2]);
            float2 c3 = __half22float2(tp[3]);
            float4 z;
            z.x = xs.x + xlo.x + fmaf(frac, c0.y - c0.x, c0.x);
            z.y = xs.y + xlo.y + fmaf(frac, c1.y - c1.x, c1.x);
            z.z = xs.z + xhi.x + fmaf(frac, c2.y - c2.x, c2.x);
            z.w = xs.w + xhi.y + fmaf(frac, c3.y - c3.x, c3.x);
            __half2 zh[2];
            zh[0] = __float22half2_rn(make_float2(z.x, z.y));
            zh[1] = __float22half2_rn(make_float2(z.z, z.w));
            *(uint2*)&g_zh[(n*MM + m)*C2 + lane*4] = *(uint2*)zh;
            float2 r0 = __half22float2(zh[0]);
            float2 r1 = __half22float2(zh[1]);
            s4.x += r0.x; s4.y += r0.y; s4.z += r1.x; s4.w += r1.y;
            q4.x = fmaf(r0.x,r0.x,q4.x); q4.y = fmaf(r0.y,r0.y,q4.y);
            q4.z = fmaf(r1.x,r1.x,q4.z); q4.w = fmaf(r1.y,r1.y,q4.w);
        }
    }
    sPart[warp][lane*4+0]=s4.x; sPart[warp][lane*4+1]=s4.y;
    sPart[warp][lane*4+2]=s4.z; sPart[warp][lane*4+3]=s4.w;
    sPart[warp][128+lane*4+0]=q4.x; sPart[warp][128+lane*4+1]=q4.y;
    sPart[warp][128+lane*4+2]=q4.z; sPart[warp][128+lane*4+3]=q4.w;
    __syncthreads();
    int t = threadIdx.x;
    float s = 0.f;
    #pragma unroll
    for(int w=0;w<8;w++) s += sPart[w][t];
    g_part1[blockIdx.x*256 + t] = s;
}

__global__ void k_fold1(const float* __restrict__ g1, const float* __restrict__ b1){
    int t = threadIdx.x;   // 128
    float s = 0.f, q = 0.f;
    for(int b=0;b<GRIDN;b++){ s += g_part1[b*256+t]; q += g_part1[b*256+128+t]; }
    const float inv = 1.0f/(float)NEDGE;
    float mean = s*inv;
    float var  = q*inv - mean*mean;
    float sc = g1[t] * rsqrtf(var + EPSF);
    g_scale1[t] = sc;
    g_shift1[t] = b1[t] - mean*sc;
}

// ---------------- pass2: fp16 z read -> BN1 -> table gate -> nbr-sum -> stats ----------------
__global__ __launch_bounds__(256) void k_pass2(){
    __shared__ float sc[C2], sh[C2];
    __shared__ float2 sTs[TABN+2], sTt[TABN+2];
    __shared__ float sPart[8][128];
    if(threadIdx.x < C2){ sc[threadIdx.x] = g_scale1[threadIdx.x]; sh[threadIdx.x] = g_shift1[threadIdx.x]; }
    for(int i=threadIdx.x;i<=TABN;i+=256){ sTs[i] = g_tsig[i]; sTt[i] = g_ttail[i]; }
    __syncthreads();
    const int warp = threadIdx.x >> 5, lane = threadIdx.x & 31;
    const int c0 = lane*2;
    float scf0 = sc[c0], scf1 = sc[c0+1], shf0 = sh[c0], shf1 = sh[c0+1];
    float scc0 = sc[AFL+c0], scc1 = sc[AFL+c0+1], shc0 = sh[AFL+c0], shc1 = sh[AFL+c0+1];
    float s0=0.f,s1=0.f,q0=0.f,q1=0.f;
    for(int n = blockIdx.x*8 + warp; n < NATOMS; n += GRIDN*8){
        float a0=0.f, a1=0.f;
        #pragma unroll 1
        for(int m=0;m<MM;m++){
            const __half* ez = &g_zh[(n*MM + m)*C2];
            float2 zf = __half22float2(*(const __half2*)&ez[c0]);
            float2 zc = __half22float2(*(const __half2*)&ez[AFL + c0]);
            float f0 = fmaf(zf.x, scf0, shf0);
            float f1 = fmaf(zf.y, scf1, shf1);
            float h0 = fmaf(zc.x, scc0, shc0);
            float h1 = fmaf(zc.y, scc1, shc1);
            float af0 = fminf(fabsf(f0)*64.f, (float)(TABN-1));
            float af1 = fminf(fabsf(f1)*64.f, (float)(TABN-1));
            int i0 = (int)af0, i1 = (int)af1;
            float2 e0 = sTs[i0], e1 = sTs[i1];
            float sg0 = fmaf(af0-(float)i0, e0.y, e0.x);
            float sg1 = fmaf(af1-(float)i1, e1.y, e1.x);
            sg0 = (f0 < 0.f) ? 1.f - sg0 : sg0;
            sg1 = (f1 < 0.f) ? 1.f - sg1 : sg1;
            float ah0 = fminf(fabsf(h0)*64.f, (float)(TABN-1));
            float ah1 = fminf(fabsf(h1)*64.f, (float)(TABN-1));
            int j0 = (int)ah0, j1 = (int)ah1;
            float2 t0 = sTt[j0], t1 = sTt[j1];
            float sp0 = fmaxf(h0,0.f) + fmaf(ah0-(float)j0, t0.y, t0.x);
            float sp1 = fmaxf(h1,0.f) + fmaf(ah1-(float)j1, t1.y, t1.x);
            a0 = fmaf(sg0, sp0, a0);
            a1 = fmaf(sg1, sp1, a1);
        }
        *(float2*)&g_summed[n*AFL + c0] = make_float2(a0, a1);
        s0 += a0; s1 += a1;
        q0 = fmaf(a0,a0,q0); q1 = fmaf(a1,a1,q1);
    }
    sPart[warp][c0]   = s0; sPart[warp][c0+1]   = s1;
    sPart[warp][AFL+c0] = q0; sPart[warp][AFL+c0+1] = q1;
    __syncthreads();
    int t = threadIdx.x;
    if(t < 128){
        float s = 0.f;
        #pragma unroll
        for(int w=0;w<8;w++) s += sPart[w][t];
        g_part2[blockIdx.x*128 + t] = s;
    }
}

__global__ void k_fold2(const float* __restrict__ g2, const float* __restrict__ b2){
    int t = threadIdx.x;   // 64
    float s = 0.f, q = 0.f;
    for(int b=0;b<GRIDN;b++){ s += g_part2[b*128+t]; q += g_part2[b*128+64+t]; }
    const float inv = 1.0f/(float)NATOMS;
    float mean = s*inv;
    float var  = q*inv - mean*mean;
    float sc = g2[t] * rsqrtf(var + EPSF);
    g_scale2[t] = sc;
    g_shift2[t] = b2[t] - mean*sc;
}

__global__ void k_update(){
    int i = blockIdx.x*blockDim.x + threadIdx.x;
    if(i < NATOMS*AFL){
        int c = i & (AFL-1);
        float v = g_x[i] + fmaf(g_summed[i], g_scale2[c], g_shift2[c]);
        g_x[i] = fmaxf(v,0.f) + log1pf(expf(-fabsf(v)));
    }
}

// ---------------- pooling + MLP head ----------------
__global__ void k_pool(const int* __restrict__ cnt, const float* __restrict__ fcW,
                       const float* __restrict__ fcb, const float* __restrict__ foW,
                       const float* __restrict__ fob, float* __restrict__ out){
    const int cid = blockIdx.x, t = threadIdx.x, w = t>>5, l = t&31;
    __shared__ float sm[AFL];
    __shared__ int sip[4];
    __shared__ float sfp[4];
    int part = 0;
    for(int i=t; i<cid; i+=128) part += cnt[i];
    for(int o=16;o;o>>=1) part += __shfl_down_sync(FULLM, part, o);
    if(l==0) sip[w] = part;
    __syncthreads();
    const int off = sip[0]+sip[1]+sip[2]+sip[3];
    const int c = cnt[cid];
    if(t < AFL){
        float s = 0.f;
        for(int a=0;a<c;a++) s += g_x[(off+a)*AFL + t];
        float v = s/(float)c;
        sm[t] = fmaxf(v,0.f) + log1pf(expf(-fabsf(v)));
    }
    __syncthreads();
    float h = fcb[t];
    for(int k=0;k<AFL;k++) h = fmaf(sm[k], fcW[k*HFL + t], h);
    h = fmaxf(h,0.f) + log1pf(expf(-fabsf(h)));
    float v = h * foW[t];
    for(int o=16;o;o>>=1) v += __shfl_down_sync(FULLM, v, o);
    if(l==0) sfp[w] = v;
    __syncthreads();
    if(t==0) out[cid] = sfp[0]+sfp[1]+sfp[2]+sfp[3] + fob[0];
}

// ---------------- launch ----------------
extern "C" void kernel_launch(void* const* d_in, const int* in_sizes, int n_in,
                              void* d_out, int out_size){
    const int*   atom_fea   = (const int*)  d_in[0];
    const float* nbr_fea    = (const float*)d_in[1];
    const int*   nbr_idx    = (const int*)  d_in[2];
    const int*   cnt        = (const int*)  d_in[3];
    const float* atom_table = (const float*)d_in[4];
    const float* W_embed    = (const float*)d_in[5];
    const float* W_conv     = (const float*)d_in[6];
    const float* b_conv     = (const float*)d_in[7];
    const float* bn1_g      = (const float*)d_in[8];
    const float* bn1_b      = (const float*)d_in[9];
    const float* bn2_g      = (const float*)d_in[10];
    const float* bn2_b      = (const float*)d_in[11];
    const float* fc_W       = (const float*)d_in[12];
    const float* fc_b       = (const float*)d_in[13];
    const float* fo_W       = (const float*)d_in[14];
    const float* fo_b       = (const float*)d_in[15];
    float* out = (float*)d_out;

    k_tab<<<4, 256>>>();
    k_embed<<<NTYPES, AFL>>>(atom_table, W_embed);
    k_gatherx<<<(NATOMS*AFL + 255)/256, 256>>>(atom_fea);

    for(int l=0;l<NCONV;l++){
        const float* W = W_conv + l*(2*AFL+EFL)*C2;
        k_ctab<<<DBINS, 128>>>(W);
        k_gemm<<<dim3(296,2), 256>>>(W);
        k_pass1<<<GRIDN, 256>>>(b_conv + l*C2, nbr_idx, nbr_fea);
        k_fold1<<<1, 128>>>(bn1_g + l*C2, bn1_b + l*C2);
        k_pass2<<<GRIDN, 256>>>();
        k_fold2<<<1, 64>>>(bn2_g + l*AFL, bn2_b + l*AFL);
        k_update<<<(NATOMS*AFL + 255)/256, 256>>>();
    }
    k_pool<<<NCRYS, 128>>>(cnt, fc_W, fc_b, fo_W, fo_b, out);
}